// round 17
// baseline (speedup 1.0000x reference)
#include <cuda_runtime.h>
#include <cuda_fp16.h>
#include <cstdint>

#define BATCHN 2
#define SEQ    2048
#define DIM    1024
#define NHEAD  16
#define HDIM   64
#define MTOT   (BATCHN*SEQ)   // 4096
#define NQB2   (SEQ/256)      // 8 attention q-blocks (256 rows each)

// ---------------- scratch (no allocs; raw u16) ----------------
__device__ unsigned short g_q[(size_t)BATCHN*NHEAD*SEQ*HDIM];   // [B,H,S,Hd] f16
__device__ unsigned short g_k[(size_t)BATCHN*NHEAD*SEQ*HDIM];
__device__ unsigned short g_v[(size_t)BATCHN*NHEAD*SEQ*HDIM];
__device__ unsigned short g_ctx[(size_t)MTOT*DIM];              // [B*S, D] f16
__device__ unsigned short g_xr[(size_t)MTOT*DIM];               // input f16
__device__ unsigned short g_wf[(size_t)4*DIM*DIM];              // W f16 [K,N]: Wq,Wk,Wv,Wo

// ---------------- helpers (compute_103-baseline PTX only) ----------------
__device__ __forceinline__ uint32_t smem_u32(const void* p) {
    uint32_t a;
    asm("{ .reg .u64 t; cvta.to.shared.u64 t, %1; cvt.u32.u64 %0, t; }" : "=r"(a) : "l"(p));
    return a;
}
__device__ __forceinline__ uint32_t pack_h2(float lo, float hi) {
    __half2 h = __floats2half2_rn(lo, hi);
    return *reinterpret_cast<uint32_t*>(&h);
}
__device__ __forceinline__ void cpasync16(uint32_t dst, const void* src) {
    asm volatile("cp.async.cg.shared.global [%0], [%1], 16;" :: "r"(dst), "l"(src));
}
#define CP_COMMIT() asm volatile("cp.async.commit_group;" ::: "memory")
#define CP_WAIT(n)  asm volatile("cp.async.wait_group %0;" :: "n"(n) : "memory")

__device__ __forceinline__ void ldsm4(uint32_t& r0, uint32_t& r1, uint32_t& r2,
                                      uint32_t& r3, uint32_t a) {
    asm volatile("ldmatrix.sync.aligned.m8n8.x4.shared.b16 {%0,%1,%2,%3}, [%4];"
                 : "=r"(r0), "=r"(r1), "=r"(r2), "=r"(r3) : "r"(a));
}
__device__ __forceinline__ void ldsm4t(uint32_t& r0, uint32_t& r1, uint32_t& r2,
                                       uint32_t& r3, uint32_t a) {
    asm volatile("ldmatrix.sync.aligned.m8n8.x4.trans.shared.b16 {%0,%1,%2,%3}, [%4];"
                 : "=r"(r0), "=r"(r1), "=r"(r2), "=r"(r3) : "r"(a));
}
// D(fp32) += A(f16 m16k16, row) * B(f16 k16n8, col)
__device__ __forceinline__ void mma_f16(float* d, const uint32_t* a, const uint32_t* b) {
    asm volatile("mma.sync.aligned.m16n8k16.row.col.f32.f16.f16.f32 "
                 "{%0,%1,%2,%3}, {%4,%5,%6,%7}, {%8,%9}, {%0,%1,%2,%3};"
                 : "+f"(d[0]), "+f"(d[1]), "+f"(d[2]), "+f"(d[3])
                 : "r"(a[0]), "r"(a[1]), "r"(a[2]), "r"(a[3]), "r"(b[0]), "r"(b[1]));
}
// D(f16x2 pair) += A * B   (f16 accumulators; C-frag == PV A-frag layout)
__device__ __forceinline__ void mma_f16acc(uint32_t* d, const uint32_t* a, const uint32_t* b) {
    asm volatile("mma.sync.aligned.m16n8k16.row.col.f16.f16.f16.f16 "
                 "{%0,%1}, {%2,%3,%4,%5}, {%6,%7}, {%0,%1};"
                 : "+r"(d[0]), "+r"(d[1])
                 : "r"(a[0]), "r"(a[1]), "r"(a[2]), "r"(a[3]), "r"(b[0]), "r"(b[1]));
}

// ---------------------------------------------------------------------------
// prep: pure elementwise fp32 -> f16 round. z<4: W_z (no transpose, [K,N]
// layout kept). z==4: input x. One launch, no smem.
// ---------------------------------------------------------------------------
__global__ void prep_kernel(const float* __restrict__ x,
                            const float* __restrict__ Wq, const float* __restrict__ Wk,
                            const float* __restrict__ Wv, const float* __restrict__ Wo,
                            unsigned short* __restrict__ xr,
                            unsigned short* __restrict__ Wf) {
    int t = threadIdx.y * 32 + threadIdx.x;
    int bid = blockIdx.y * 32 + blockIdx.x;          // 0..1023
    if (blockIdx.z == 4) {                            // x: 1M float4s
        #pragma unroll
        for (int j = 0; j < 4; j++) {
            int i = bid * 1024 + j * 256 + t;
            float4 v = reinterpret_cast<const float4*>(x)[i];
            uint2 o = { pack_h2(v.x, v.y), pack_h2(v.z, v.w) };
            reinterpret_cast<uint2*>(xr)[i] = o;
        }
        return;
    }
    int z = blockIdx.z;
    const float* W = (z == 0) ? Wq : (z == 1) ? Wk : (z == 2) ? Wv : Wo;
    unsigned short* dst = Wf + (size_t)z * DIM * DIM;
    int i = bid * 256 + t;                            // over float4s (256K per W)
    float4 v = reinterpret_cast<const float4*>(W)[i];
    uint2 o = { pack_h2(v.x, v.y), pack_h2(v.z, v.w) };
    reinterpret_cast<uint2*>(dst)[i] = o;
}

// ---------------------------------------------------------------------------
// GEMM (mma.sync f16, fp32 accum): CTA 256x128, BK=128, 2-stage cp.async,
// fragment software pipeline. B = W in natural [K,N] layout; B-fragments via
// ldmatrix.trans (same fill/read swizzle as the proven attention V path).
// smem/stage: A 64KB (two 32KB k-halves), B 32KB (two 16KB n-halves). 192KB.
// MODE 0: out[4096,1024] fp32 row-major (W = Wf+3M). MODE 1: fused QKV
//         (N=3072, seg n0>>10 selects W seg / bias / dest), f16 scatter.
// ---------------------------------------------------------------------------
#define GEMM_SMEM 196608

template<int MODE>
__global__ void __launch_bounds__(256, 1)
gemm_mma(const unsigned short* __restrict__ A, const unsigned short* __restrict__ Wf,
         const float* __restrict__ b0p, const float* __restrict__ b1p,
         const float* __restrict__ b2p,
         void* __restrict__ o0, void* __restrict__ o1, void* __restrict__ o2)
{
    extern __shared__ char smem[];
    const uint32_t sb = smem_u32(smem);
    const int tid = threadIdx.x, lane = tid & 31, wid = tid >> 5;
    const int wm = wid >> 1, wn = wid & 1;
    const int m0 = blockIdx.y * 256, n0 = blockIdx.x * 128;

    // B source: W segment + local n base
    const unsigned short* Wseg;
    int nbase;
    if (MODE == 0) { Wseg = Wf + (size_t)3 * DIM * DIM; nbase = n0; }
    else           { Wseg = Wf + (size_t)(n0 >> 10) * DIM * DIM; nbase = n0 & 1023; }

    float acc[4][8][4];
    #pragma unroll
    for (int i = 0; i < 4; i++)
        #pragma unroll
        for (int j = 0; j < 8; j++)
            #pragma unroll
            for (int r = 0; r < 4; r++) acc[i][j][r] = 0.0f;

    auto load_chunk = [&](int st, int k0) {
        uint32_t ab = sb + st * 98304, bb = ab + 65536;
        #pragma unroll
        for (int i = 0; i < 16; i++) {      // A: 256 m-rows x 16 k-quads
            int idx = tid + i * 256, r = idx >> 4, c = idx & 15;
            cpasync16(ab + (c >> 3) * 32768 + r * 128 + 16 * ((c & 7) ^ (r & 7)),
                      A + (size_t)(m0 + r) * DIM + k0 + c * 8);
        }
        #pragma unroll
        for (int i = 0; i < 8; i++) {       // B (W [K,N]): 128 k-rows x 16 n-quads
            int idx = tid + i * 256, r = idx >> 4, c = idx & 15;
            cpasync16(bb + (c >> 3) * 16384 + r * 128 + 16 * ((c & 7) ^ (r & 7)),
                      Wseg + (size_t)(k0 + r) * DIM + nbase + c * 8);
        }
        CP_COMMIT();
    };

    load_chunk(0, 0);
    for (int ch = 0; ch < 8; ch++) {        // BK=128, K=1024
        int st = ch & 1;
        __syncthreads();
        if (ch + 1 < 8) { load_chunk(st ^ 1, (ch + 1) * 128); CP_WAIT(1); }
        else            { CP_WAIT(0); }
        __syncthreads();

        uint32_t ab = sb + st * 98304;
        uint32_t bb = sb + st * 98304 + 65536 + wn * 16384;   // this warp's n-half
        uint32_t af[2][4][4], bf[2][4][4];

        auto loadA = [&](int ks, uint32_t (*a)[4]) {
            #pragma unroll
            for (int mt = 0; mt < 4; mt++) {
                int row = wm * 64 + mt * 16 + (lane & 15);
                int at  = 2 * ks + (lane >> 4);
                ldsm4(a[mt][0], a[mt][1], a[mt][2], a[mt][3],
                      ab + (at >> 3) * 32768 + row * 128 + 16 * ((at & 7) ^ (row & 7)));
            }
        };
        // B frags via ldsm.trans on [K,N] tile (mirror of attention V path)
        auto loadB = [&](int ks, uint32_t (*b)[4]) {
            #pragma unroll
            for (int pr = 0; pr < 4; pr++) {
                int k = ks * 16 + (lane & 7) + (((lane >> 3) & 1) ? 8 : 0);
                int q = 2 * pr + ((lane >> 4) & 1);
                ldsm4t(b[pr][0], b[pr][1], b[pr][2], b[pr][3],
                       bb + k * 128 + 16 * (q ^ (k & 7)));
            }
        };

        loadA(0, af[0]);
        loadB(0, bf[0]);
        #pragma unroll
        for (int ks = 0; ks < 8; ks++) {
            int cur = ks & 1;
            if (ks + 1 < 8) {
                loadA(ks + 1, af[cur ^ 1]);
                loadB(ks + 1, bf[cur ^ 1]);
            }
            #pragma unroll
            for (int mt = 0; mt < 4; mt++)
                #pragma unroll
                for (int pr = 0; pr < 4; pr++) {
                    mma_f16(acc[mt][2 * pr],     af[cur][mt], &bf[cur][pr][0]);
                    mma_f16(acc[mt][2 * pr + 1], af[cur][mt], &bf[cur][pr][2]);
                }
        }
    }

    // epilogue
    const float* bias;
    unsigned short* outh = nullptr;
    float* outf = nullptr;
    if (MODE == 0) { bias = b0p; outf = (float*)o0; }
    else {
        int seg = n0 >> 10;
        bias = (seg == 0) ? b0p : (seg == 1) ? b1p : b2p;
        outh = (unsigned short*)((seg == 0) ? o0 : (seg == 1) ? o1 : o2);
    }
    const int rb = m0 + wm * 64 + (lane >> 2);
    const int cb = (MODE == 0 ? n0 : (n0 & 1023)) + wn * 64 + 2 * (lane & 3);
    #pragma unroll
    for (int mt = 0; mt < 4; mt++) {
        #pragma unroll
        for (int nf = 0; nf < 8; nf++) {
            int r = rb + mt * 16, c = cb + nf * 8;
            float b0 = bias[c], b1 = bias[c + 1];
            float x0 = acc[mt][nf][0] + b0, x1 = acc[mt][nf][1] + b1;
            float x2 = acc[mt][nf][2] + b0, x3 = acc[mt][nf][3] + b1;
            if (MODE == 0) {
                float2 v0 = {x0, x1}, v1 = {x2, x3};
                *reinterpret_cast<float2*>(outf + (size_t)r * DIM + c) = v0;
                *reinterpret_cast<float2*>(outf + (size_t)(r + 8) * DIM + c) = v1;
            } else {
                int bt = r >> 11, h = c >> 6, hd = c & 63;
                size_t base = (((size_t)(bt * NHEAD + h)) * SEQ) * HDIM + hd;
                *reinterpret_cast<uint32_t*>(outh + base + (size_t)(r & 2047) * HDIM) =
                    pack_h2(x0, x1);
                *reinterpret_cast<uint32_t*>(outh + base + (size_t)((r + 8) & 2047) * HDIM) =
                    pack_h2(x2, x3);
            }
        }
    }
}

// ---------------------------------------------------------------------------
// Flash attention. CTA = 256 q-rows, 8 warps x m32. f16-accum QK^T.
// 128-wide kv chunks, 4 stages x 32KB. NEW: row-sums l computed on the
// fma/alu pipes (hadd2 + cvt + fadd, fp32 accumulation) instead of ones-mma
// -- removes ~6% of tensor-pipe instructions.
// ---------------------------------------------------------------------------
#define ATTN_SMEM 131072

__global__ void __launch_bounds__(256, 1)
flash_attn_mma(const unsigned short* __restrict__ gq,
               const unsigned short* __restrict__ gk,
               const unsigned short* __restrict__ gv,
               unsigned short* __restrict__ ctx)
{
    extern __shared__ char smem[];
    const uint32_t sb = smem_u32(smem);
    const int tid = threadIdx.x, lane = tid & 31, wid = tid >> 5;
    const int bh = blockIdx.y, b = bh >> 4, h = bh & 15;

    const unsigned short* kbase = gk + (size_t)bh * SEQ * HDIM;
    const unsigned short* vbase = gv + (size_t)bh * SEQ * HDIM;

    const __half2 c_sc2   = __float2half2_rn(0.18033688011112042f);  // (1/8)*log2(e)
    const __half2 c_negM  = __float2half2_rn(-6.0f);
    const __half2 c_clamp = __float2half2_rn(15.0f);

    auto p_of = [&](uint32_t packed_sc) -> uint32_t {  // P = ex2(min(s*SC2-M,15))
        __half2 u = *reinterpret_cast<__half2*>(&packed_sc);
        __half2 y = __hmin2(__hfma2(u, c_sc2, c_negM), c_clamp);
        uint32_t r;
        asm("ex2.approx.f16x2 %0, %1;" : "=r"(r) : "r"(*reinterpret_cast<uint32_t*>(&y)));
        return r;
    };

    auto loadKV = [&](int t2, int st) {     // one 128-row kv chunk (K + V)
        uint32_t kb = sb + st * 32768, vb = kb + 16384;
        #pragma unroll
        for (int i = 0; i < 4; i++) {
            int idx = tid + i * 256, r = idx >> 3, c = idx & 7;
            uint32_t off = r * 128 + 16 * (c ^ (r & 7));
            const unsigned short* s = kbase + (size_t)(t2 * 128 + r) * 64 + c * 8;
            cpasync16(kb + off, s);
            cpasync16(vb + off, vbase + (s - kbase));
        }
        CP_COMMIT();
    };

    #pragma unroll 1
    for (int pass = 0; pass < 2; pass++) {
        const int qb = pass ? (NQB2 - 1 - blockIdx.x) : blockIdx.x;
        const int nt2 = 2 * qb + 2;
        const unsigned short* qg =
            gq + ((size_t)bh * SEQ + qb * 256 + wid * 32) * HDIM;

        uint32_t qf[2][4][4];
        {
            int r = lane >> 2, c2 = 2 * (lane & 3);
            #pragma unroll
            for (int hf = 0; hf < 2; hf++) {
                const unsigned short* qh = qg + hf * 16 * HDIM;
                #pragma unroll
                for (int ks = 0; ks < 4; ks++) {
                    qf[hf][ks][0] = *reinterpret_cast<const uint32_t*>(qh + r * 64 + ks * 16 + c2);
                    qf[hf][ks][1] = *reinterpret_cast<const uint32_t*>(qh + (r + 8) * 64 + ks * 16 + c2);
                    qf[hf][ks][2] = *reinterpret_cast<const uint32_t*>(qh + r * 64 + ks * 16 + 8 + c2);
                    qf[hf][ks][3] = *reinterpret_cast<const uint32_t*>(qh + (r + 8) * 64 + ks * 16 + 8 + c2);
                }
            }
        }

        float O[2][8][4];
        #pragma unroll
        for (int hf = 0; hf < 2; hf++)
            #pragma unroll
            for (int i = 0; i < 8; i++)
                #pragma unroll
                for (int j = 0; j < 4; j++) O[hf][i][j] = 0.0f;
        float lr[2][2] = {{0.0f, 0.0f}, {0.0f, 0.0f}};   // per-lane partial l

        __syncthreads();
        loadKV(0, 0);
        if (nt2 > 1) loadKV(1, 1);
        if (nt2 > 2) loadKV(2, 2);

        const int row0g = qb * 256 + wid * 32 + (lane >> 2);

        for (int t2 = 0; t2 < nt2; t2++) {
            int st = t2 & 3;
            if (t2 + 2 < nt2)      CP_WAIT(2);
            else if (t2 + 1 < nt2) CP_WAIT(1);
            else                   CP_WAIT(0);
            __syncthreads();
            if (t2 + 3 < nt2) loadKV(t2 + 3, (t2 + 3) & 3);

            #pragma unroll
            for (int s = 0; s < 2; s++) {
                const int t = 2 * t2 + s;
                const bool diag = (t >= 4 * qb);
                const int  tl   = t - 4 * qb;
                if (diag && tl * 64 > wid * 32 + 31) continue;   // P==0, skip

                uint32_t sc2[2][8][2];
                #pragma unroll
                for (int hf = 0; hf < 2; hf++)
                    #pragma unroll
                    for (int i = 0; i < 8; i++) {
                        sc2[hf][i][0] = 0u; sc2[hf][i][1] = 0u;
                    }

                uint32_t kb = sb + st * 32768 + s * 8192;
                #pragma unroll
                for (int ks = 0; ks < 4; ks++) {
                    #pragma unroll
                    for (int pr = 0; pr < 4; pr++) {
                        int row = pr * 16 + (lane & 7) + ((lane & 16) ? 8 : 0);
                        int at  = 2 * ks + ((lane >> 3) & 1);
                        uint32_t bfr[4];
                        ldsm4(bfr[0], bfr[1], bfr[2], bfr[3],
                              kb + row * 128 + 16 * (at ^ (row & 7)));
                        #pragma unroll
                        for (int hf = 0; hf < 2; hf++) {
                            mma_f16acc(sc2[hf][2 * pr],     qf[hf][ks], &bfr[0]);
                            mma_f16acc(sc2[hf][2 * pr + 1], qf[hf][ks], &bfr[2]);
                        }
                    }
                }

                if (diag && tl * 64 + 63 > wid * 32) {
                    #pragma unroll
                    for (int hf = 0; hf < 2; hf++) {
                        int r0 = row0g + hf * 16;
                        #pragma unroll
                        for (int nt = 0; nt < 8; nt++) {
                            int col = t * 64 + nt * 8 + 2 * (lane & 3);
                            uint32_t s0 = sc2[hf][nt][0];
                            if (col > r0)          s0 = 0xFC00FC00u;
                            else if (col + 1 > r0) s0 = (s0 & 0xFFFFu) | 0xFC000000u;
                            sc2[hf][nt][0] = s0;
                            uint32_t s1 = sc2[hf][nt][1];
                            if (col > r0 + 8)          s1 = 0xFC00FC00u;
                            else if (col + 1 > r0 + 8) s1 = (s1 & 0xFFFFu) | 0xFC000000u;
                            sc2[hf][nt][1] = s1;
                        }
                    }
                }

                uint32_t vb = sb + st * 32768 + 16384 + s * 8192;
                #pragma unroll
                for (int ks = 0; ks < 4; ks++) {
                    uint32_t pa[2][4];
                    #pragma unroll
                    for (int hf = 0; hf < 2; hf++) {
                        pa[hf][0] = p_of(sc2[hf][2 * ks][0]);
                        pa[hf][1] = p_of(sc2[hf][2 * ks][1]);
                        pa[hf][2] = p_of(sc2[hf][2 * ks + 1][0]);
                        pa[hf][3] = p_of(sc2[hf][2 * ks + 1][1]);
                        // l on fma pipe: rows r (pa0,pa2) and r+8 (pa1,pa3)
                        __half2 hA = __hadd2(*reinterpret_cast<__half2*>(&pa[hf][0]),
                                             *reinterpret_cast<__half2*>(&pa[hf][2]));
                        __half2 hB = __hadd2(*reinterpret_cast<__half2*>(&pa[hf][1]),
                                             *reinterpret_cast<__half2*>(&pa[hf][3]));
                        float2 fA = __half22float2(hA);
                        float2 fB = __half22float2(hB);
                        lr[hf][0] += fA.x + fA.y;
                        lr[hf][1] += fB.x + fB.y;
                    }
                    #pragma unroll
                    for (int hp = 0; hp < 4; hp++) {
                        int kv = ks * 16 + (lane & 7) + (((lane >> 3) & 1) ? 8 : 0);
                        int q  = 2 * hp + ((lane >> 4) & 1);
                        uint32_t bfr[4];
                        ldsm4t(bfr[0], bfr[1], bfr[2], bfr[3],
                               vb + kv * 128 + 16 * (q ^ (kv & 7)));
                        #pragma unroll
                        for (int hf = 0; hf < 2; hf++) {
                            mma_f16(O[hf][2 * hp],     pa[hf], &bfr[0]);
                            mma_f16(O[hf][2 * hp + 1], pa[hf], &bfr[2]);
                        }
                    }
                }
            }
        }

        #pragma unroll
        for (int hf = 0; hf < 2; hf++) {
            float l0 = lr[hf][0], l1 = lr[hf][1];
            l0 += __shfl_xor_sync(0xffffffffu, l0, 1);
            l0 += __shfl_xor_sync(0xffffffffu, l0, 2);
            l1 += __shfl_xor_sync(0xffffffffu, l1, 1);
            l1 += __shfl_xor_sync(0xffffffffu, l1, 2);
            lr[hf][0] = 0.0f; lr[hf][1] = 0.0f;   // reset for next pass
            float inv0 = 1.0f / l0, inv1 = 1.0f / l1;
            unsigned short* cb0 = ctx + ((size_t)b * SEQ + row0g + hf * 16) * DIM
                                  + h * 64 + 2 * (lane & 3);
            #pragma unroll
            for (int nt = 0; nt < 8; nt++) {
                *reinterpret_cast<uint32_t*>(cb0 + nt * 8) =
                    pack_h2(O[hf][nt][0] * inv0, O[hf][nt][1] * inv0);
                *reinterpret_cast<uint32_t*>(cb0 + (size_t)8 * DIM + nt * 8) =
                    pack_h2(O[hf][nt][2] * inv1, O[hf][nt][3] * inv1);
            }
        }
    }
}

// ---------------------------------------------------------------------------
extern "C" void kernel_launch(void* const* d_in, const int* in_sizes, int n_in,
                              void* d_out, int out_size)
{
    const float* x  = (const float*)d_in[0];
    const float* Wq = (const float*)d_in[1];
    const float* bq = (const float*)d_in[2];
    const float* Wk = (const float*)d_in[3];
    const float* bk = (const float*)d_in[4];
    const float* Wv = (const float*)d_in[5];
    const float* bv = (const float*)d_in[6];
    const float* Wo = (const float*)d_in[7];
    const float* bo = (const float*)d_in[8];
    float* out = (float*)d_out;

    unsigned short *q, *k, *v, *ctx, *xr, *wf;
    cudaGetSymbolAddress((void**)&q,   g_q);
    cudaGetSymbolAddress((void**)&k,   g_k);
    cudaGetSymbolAddress((void**)&v,   g_v);
    cudaGetSymbolAddress((void**)&ctx, g_ctx);
    cudaGetSymbolAddress((void**)&xr,  g_xr);
    cudaGetSymbolAddress((void**)&wf,  g_wf);

    cudaFuncSetAttribute(gemm_mma<0>, cudaFuncAttributeMaxDynamicSharedMemorySize, GEMM_SMEM);
    cudaFuncSetAttribute(gemm_mma<1>, cudaFuncAttributeMaxDynamicSharedMemorySize, GEMM_SMEM);
    cudaFuncSetAttribute(flash_attn_mma, cudaFuncAttributeMaxDynamicSharedMemorySize, ATTN_SMEM);

    // 1. prep: elementwise round of x and the four W (one launch, no smem)
    dim3 gp(32, 32, 5), bp(32, 8);
    prep_kernel<<<gp, bp>>>(x, Wq, Wk, Wv, Wo, xr, wf);
    // 2. fused QKV projection (N = 3072), B via ldsm.trans on [K,N] W
    dim3 gqkv(3 * DIM / 128, MTOT / 256);   // (24, 16)
    gemm_mma<1><<<gqkv, 256, GEMM_SMEM>>>(xr, wf, bq, bk, bv, q, k, v);
    // 3. attention (256-row CTAs, paired causal blocks, 128-wide kv chunks)
    dim3 ga(NQB2 / 2, BATCHN * NHEAD);      // (4, 32)
    flash_attn_mma<<<ga, 256, ATTN_SMEM>>>(q, k, v, ctx);
    // 4. output projection -> 128 CTAs (single wave)
    dim3 go(DIM / 128, MTOT / 256);         // (8, 16)
    gemm_mma<0><<<go, 256, GEMM_SMEM>>>(ctx, wf, bo, nullptr, nullptr,
                                        out, nullptr, nullptr);
}